// round 1
// baseline (speedup 1.0000x reference)
#include <cuda_runtime.h>
#include <math.h>

#define DD 64
#define CC 256
#define RR 128
#define NPTS 100000
#define VV (DD*DD*DD)

// ---------------- scratch (static device globals; no allocations) ----------
__device__ int   g_idx[VV];                      // voxel -> point index or -1
__device__ float g_t1[(size_t)VV * CC];          // pass buffer A (also reused as pooled y)
__device__ float g_t2[(size_t)VV * CC];          // pass buffer B

#define NEGINF (-INFINITY)

// ---------------- index grid ----------------------------------------------
__global__ void k_init_idx() {
    int i = blockIdx.x * blockDim.x + threadIdx.x;
    if (i < VV) g_idx[i] = -1;
}

__global__ void k_scatter(const int* __restrict__ coords) {
    int i = blockIdx.x * blockDim.x + threadIdx.x;
    if (i < NPTS) {
        int ix = coords[3*i], iy = coords[3*i+1], iz = coords[3*i+2];
        g_idx[(ix*DD + iy)*DD + iz] = i;
    }
}

// ---------------- separable 7-tap max pool, sliding window in registers ----
#define SHIFTIN(v) do { w6=w5; w5=w4; w4=w3; w3=w2; w2=w1; w1=w0; w0=(v); } while(0)
#define MAX7 fmaxf(fmaxf(fmaxf(w0,w1),fmaxf(w2,w3)),fmaxf(fmaxf(w4,w5),w6))

// z-pass: reads feats through the index grid (grid never materialized), writes g_t1 dense.
__global__ __launch_bounds__(256) void k_pool_z(const float* __restrict__ feats) {
    int col = blockIdx.x;          // x*64 + y
    int c   = threadIdx.x;         // channel
    size_t base = (size_t)col * DD;
    __shared__ int pid[DD];
    if (c < DD) pid[c] = g_idx[base + c];
    __syncthreads();

    float w0,w1,w2,w3,w4,w5,w6;
    w0=w1=w2=w3=w4=w5=w6 = NEGINF;
    #pragma unroll
    for (int zz = 0; zz < 3; zz++) {
        int p = pid[zz];
        float v = (p >= 0) ? feats[(size_t)p*CC + c] : NEGINF;
        SHIFTIN(v);
    }
    #pragma unroll 4
    for (int z = 0; z < DD; z++) {
        int zz = z + 3;
        float v = NEGINF;
        if (zz < DD) { int p = pid[zz]; if (p >= 0) v = feats[(size_t)p*CC + c]; }
        SHIFTIN(v);
        g_t1[(base + z)*CC + c] = MAX7;
    }
}

// y-pass: dense g_t1 -> g_t2
__global__ __launch_bounds__(256) void k_pool_y() {
    int col = blockIdx.x;          // x*64 + z
    int x = col >> 6, z = col & 63;
    int c = threadIdx.x;
    size_t base = (size_t)x * 4096 + z;     // lin(y) = base + y*64

    float w0,w1,w2,w3,w4,w5,w6;
    w0=w1=w2=w3=w4=w5=w6 = NEGINF;
    #pragma unroll
    for (int yy = 0; yy < 3; yy++) SHIFTIN(g_t1[(base + (size_t)yy*64)*CC + c]);
    #pragma unroll 4
    for (int y = 0; y < DD; y++) {
        int yy = y + 3;
        float v = (yy < DD) ? g_t1[(base + (size_t)yy*64)*CC + c] : NEGINF;
        SHIFTIN(v);
        g_t2[(base + (size_t)y*64)*CC + c] = MAX7;
    }
}

// x-pass fused with gather: dense read of g_t2, emit pooled rows only at occupied
// voxels into g_t1 (reused as y buffer, row p = point index).
__global__ __launch_bounds__(256) void k_pool_x_gather() {
    int col = blockIdx.x;          // y*64 + z
    int c = threadIdx.x;
    __shared__ int pid[DD];
    if (c < DD) pid[c] = g_idx[(size_t)c*4096 + col];
    __syncthreads();

    size_t base = (size_t)col;     // lin(x) = base + x*4096
    float w0,w1,w2,w3,w4,w5,w6;
    w0=w1=w2=w3=w4=w5=w6 = NEGINF;
    #pragma unroll
    for (int xx = 0; xx < 3; xx++) SHIFTIN(g_t2[(base + (size_t)xx*4096)*CC + c]);
    #pragma unroll 4
    for (int x = 0; x < DD; x++) {
        int xx = x + 3;
        float v = (xx < DD) ? g_t2[(base + (size_t)xx*4096)*CC + c] : NEGINF;
        SHIFTIN(v);
        int p = pid[x];
        if (p >= 0) g_t1[(size_t)p*CC + c] = MAX7;
    }
}

// ---------------- fused MLP: out = feats * sigmoid(relu(y@W1)@W2) ----------
// tf32 mma.sync (m16n8k8), 256 threads = 8 warps (4 M x 2 N), 128 rows/CTA.

__device__ __forceinline__ unsigned f2tf(float f) {
    unsigned u; asm("cvt.rna.tf32.f32 %0, %1;" : "=r"(u) : "f"(f)); return u;
}
__device__ __forceinline__ void mma8(float* d, const unsigned* a, const unsigned* b,
                                     const float* c) {
    asm volatile("mma.sync.aligned.m16n8k8.row.col.f32.tf32.tf32.f32 "
        "{%0,%1,%2,%3}, {%4,%5,%6,%7}, {%8,%9}, {%10,%11,%12,%13};"
        : "=f"(d[0]),"=f"(d[1]),"=f"(d[2]),"=f"(d[3])
        : "r"(a[0]),"r"(a[1]),"r"(a[2]),"r"(a[3]),
          "r"(b[0]),"r"(b[1]),
          "f"(c[0]),"f"(c[1]),"f"(c[2]),"f"(c[3]));
}

#define SW1S 260                   // sW1T [128 n][260], bank = (4n+k)%32 conflict-free
#define SHS  132                   // sH   [128 m][132], bank = (4m+k)%32 conflict-free
#define SW2S 132                   // sW2T [256 n][132]
#define REGION0_WORDS 33792        // max(128*260=33280, 256*132=33792)
#define SH_OFF_WORDS  33792
#define MLP_SMEM_BYTES ((REGION0_WORDS + 128*SHS) * 4)   // 202752

__global__ __launch_bounds__(256) void k_mlp(
    const float* __restrict__ feats, const float* __restrict__ W1,
    const float* __restrict__ W2, float* __restrict__ out) {
    extern __shared__ unsigned sm[];
    unsigned* sW1T = sm;                     // phase A
    unsigned* sW2T = sm;                     // phase B (overwrites W1T after sync)
    unsigned* sH   = sm + SH_OFF_WORDS;

    int tid = threadIdx.x;
    int lane = tid & 31, wid = tid >> 5;
    int group = lane >> 2, tg = lane & 3;
    int warpM = wid & 3, warpN = wid >> 2;   // 4 x 2 warp grid
    int m0 = blockIdx.x * 128;
    const float* Y = g_t1;                   // pooled features

    // load W1 transposed (tf32 bits)
    for (int idx = tid; idx < CC*RR; idx += 256) {
        int k = idx >> 7, n = idx & 127;
        sW1T[n*SW1S + k] = f2tf(W1[idx]);
    }
    __syncthreads();

    // ---- GEMM1: H[128][128] = Y @ W1, A from global, B from smem ----
    int rowbase = warpM * 32;
    int colbase = warpN * 64;
    float acc[2][8][4];
    #pragma unroll
    for (int mt = 0; mt < 2; mt++)
        #pragma unroll
        for (int nt = 0; nt < 8; nt++)
            #pragma unroll
            for (int q = 0; q < 4; q++) acc[mt][nt][q] = 0.f;

    for (int k0 = 0; k0 < CC; k0 += 8) {
        unsigned a[2][4];
        #pragma unroll
        for (int mt = 0; mt < 2; mt++) {
            size_t r  = (size_t)(m0 + rowbase + mt*16 + group) * CC;
            size_t r8 = r + (size_t)8 * CC;
            a[mt][0] = f2tf(Y[r  + k0 + tg]);
            a[mt][1] = f2tf(Y[r8 + k0 + tg]);
            a[mt][2] = f2tf(Y[r  + k0 + tg + 4]);
            a[mt][3] = f2tf(Y[r8 + k0 + tg + 4]);
        }
        unsigned b[8][2];
        #pragma unroll
        for (int nt = 0; nt < 8; nt++) {
            int n = colbase + nt*8 + group;
            b[nt][0] = sW1T[n*SW1S + k0 + tg];
            b[nt][1] = sW1T[n*SW1S + k0 + tg + 4];
        }
        #pragma unroll
        for (int mt = 0; mt < 2; mt++)
            #pragma unroll
            for (int nt = 0; nt < 8; nt++)
                mma8(acc[mt][nt], a[mt], b[nt], acc[mt][nt]);
    }

    // relu -> sH as tf32
    #pragma unroll
    for (int mt = 0; mt < 2; mt++)
        #pragma unroll
        for (int nt = 0; nt < 8; nt++) {
            int rl = rowbase + mt*16 + group;
            int cl = colbase + nt*8 + 2*tg;
            sH[rl*SHS + cl]         = f2tf(fmaxf(acc[mt][nt][0], 0.f));
            sH[rl*SHS + cl + 1]     = f2tf(fmaxf(acc[mt][nt][1], 0.f));
            sH[(rl+8)*SHS + cl]     = f2tf(fmaxf(acc[mt][nt][2], 0.f));
            sH[(rl+8)*SHS + cl + 1] = f2tf(fmaxf(acc[mt][nt][3], 0.f));
        }
    __syncthreads();

    // load W2 transposed (overwrites W1T region)
    for (int idx = tid; idx < RR*CC; idx += 256) {
        int k = idx >> 8, n = idx & 255;
        sW2T[n*SW2S + k] = f2tf(W2[idx]);
    }
    __syncthreads();

    // ---- GEMM2: Z = relu(H) @ W2, two 64-col passes per warp ----
    for (int p = 0; p < 2; p++) {
        int cb = warpN*128 + p*64;
        float acc2[2][8][4];
        #pragma unroll
        for (int mt = 0; mt < 2; mt++)
            #pragma unroll
            for (int nt = 0; nt < 8; nt++)
                #pragma unroll
                for (int q = 0; q < 4; q++) acc2[mt][nt][q] = 0.f;

        for (int k0 = 0; k0 < RR; k0 += 8) {
            unsigned a[2][4];
            #pragma unroll
            for (int mt = 0; mt < 2; mt++) {
                int rl = rowbase + mt*16 + group;
                a[mt][0] = sH[rl*SHS + k0 + tg];
                a[mt][1] = sH[(rl+8)*SHS + k0 + tg];
                a[mt][2] = sH[rl*SHS + k0 + tg + 4];
                a[mt][3] = sH[(rl+8)*SHS + k0 + tg + 4];
            }
            unsigned b[8][2];
            #pragma unroll
            for (int nt = 0; nt < 8; nt++) {
                int n = cb + nt*8 + group;
                b[nt][0] = sW2T[n*SW2S + k0 + tg];
                b[nt][1] = sW2T[n*SW2S + k0 + tg + 4];
            }
            #pragma unroll
            for (int mt = 0; mt < 2; mt++)
                #pragma unroll
                for (int nt = 0; nt < 8; nt++)
                    mma8(acc2[mt][nt], a[mt], b[nt], acc2[mt][nt]);
        }

        // epilogue: sigmoid, multiply feats, store
        #pragma unroll
        for (int mt = 0; mt < 2; mt++)
            #pragma unroll
            for (int nt = 0; nt < 8; nt++) {
                int rl = rowbase + mt*16 + group;
                int cl = cb + nt*8 + 2*tg;
                int gi0 = m0 + rl, gi1 = gi0 + 8;
                if (gi0 < NPTS) {
                    float2 f = *(const float2*)(feats + (size_t)gi0*CC + cl);
                    float s0 = 1.f/(1.f + __expf(-acc2[mt][nt][0]));
                    float s1 = 1.f/(1.f + __expf(-acc2[mt][nt][1]));
                    float2 o; o.x = f.x*s0; o.y = f.y*s1;
                    *(float2*)(out + (size_t)gi0*CC + cl) = o;
                }
                if (gi1 < NPTS) {
                    float2 f = *(const float2*)(feats + (size_t)gi1*CC + cl);
                    float s2 = 1.f/(1.f + __expf(-acc2[mt][nt][2]));
                    float s3 = 1.f/(1.f + __expf(-acc2[mt][nt][3]));
                    float2 o; o.x = f.x*s2; o.y = f.y*s3;
                    *(float2*)(out + (size_t)gi1*CC + cl) = o;
                }
            }
    }
}

// ---------------- launch ----------------------------------------------------
extern "C" void kernel_launch(void* const* d_in, const int* in_sizes, int n_in,
                              void* d_out, int out_size) {
    const float* feats  = (const float*)d_in[0];
    const int*   coords = (const int*)d_in[1];
    const float* W1     = (const float*)d_in[2];
    const float* W2     = (const float*)d_in[3];
    float*       out    = (float*)d_out;

    k_init_idx<<<(VV + 255)/256, 256>>>();
    k_scatter<<<(NPTS + 255)/256, 256>>>(coords);
    k_pool_z<<<DD*DD, 256>>>(feats);
    k_pool_y<<<DD*DD, 256>>>();
    k_pool_x_gather<<<DD*DD, 256>>>();

    cudaFuncSetAttribute(k_mlp, cudaFuncAttributeMaxDynamicSharedMemorySize,
                         MLP_SMEM_BYTES);
    int nblk = (NPTS + 127) / 128;   // 782
    k_mlp<<<nblk, 256, MLP_SMEM_BYTES>>>(feats, W1, W2, out);
}

// round 2
// speedup vs baseline: 1.8828x; 1.8828x over previous
#include <cuda_runtime.h>
#include <cuda_fp16.h>
#include <math.h>

#define DD 64
#define CC 256
#define RR 128
#define NPTS 100000
#define VV (DD*DD*DD)

// ---------------- scratch (static device globals; no allocations) ----------
__device__ int     g_idx[VV];                     // voxel -> point index or -1
__device__ __half2 g_h1[(size_t)VV * 128];        // pass buffer A (half2: 2 ch/elem)
__device__ __half2 g_h2[(size_t)VV * 128];        // pass buffer B
__device__ __half2 g_y [(size_t)NPTS * 128];      // gathered pooled features

#define NEGINF (-INFINITY)

// ---------------- index grid ----------------------------------------------
__global__ void k_init_idx() {
    int i = blockIdx.x * blockDim.x + threadIdx.x;
    if (i < VV) g_idx[i] = -1;
}

__global__ void k_scatter(const int* __restrict__ coords) {
    int i = blockIdx.x * blockDim.x + threadIdx.x;
    if (i < NPTS) {
        int ix = coords[3*i], iy = coords[3*i+1], iz = coords[3*i+2];
        g_idx[(ix*DD + iy)*DD + iz] = i;
    }
}

// ---------------- separable 7-tap max pool (fp16), sliding windows ---------
#define SHIFT1(w, v) do { w[6]=w[5]; w[5]=w[4]; w[4]=w[3]; w[3]=w[2]; w[2]=w[1]; w[1]=w[0]; w[0]=(v); } while(0)
__device__ __forceinline__ __half2 max7h(const __half2* w) {
    return __hmax2(__hmax2(__hmax2(w[0],w[1]),__hmax2(w[2],w[3])),
                   __hmax2(__hmax2(w[4],w[5]),w[6]));
}

// z-pass: gather feats fp32 through idx grid, write dense fp16. 2 cols/block.
__global__ __launch_bounds__(256) void k_pool_z(const float* __restrict__ feats) {
    int sub = threadIdx.x >> 7;              // 0..1 : column within block
    int c2  = threadIdx.x & 127;             // half2 channel index
    int col = blockIdx.x * 2 + sub;          // x*64 + y
    size_t base = (size_t)col * DD;

    __shared__ int pid[2][DD];
    if (threadIdx.x < 128) {
        int s = threadIdx.x >> 6, zz = threadIdx.x & 63;
        pid[s][zz] = g_idx[(size_t)(blockIdx.x*2 + s)*DD + zz];
    }
    __syncthreads();

    const __half2 NEG2 = __float2half2_rn(NEGINF);
    __half2 w[7];
    #pragma unroll
    for (int i = 0; i < 7; i++) w[i] = NEG2;

    #pragma unroll
    for (int zz = 0; zz < 3; zz++) {
        int p = pid[sub][zz];
        __half2 v = NEG2;
        if (p >= 0) {
            float2 f = *(const float2*)(feats + (size_t)p*CC + 2*c2);
            v = __floats2half2_rn(f.x, f.y);
        }
        SHIFT1(w, v);
    }
    #pragma unroll 4
    for (int z = 0; z < DD; z++) {
        int zz = z + 3;
        __half2 v = NEG2;
        if (zz < DD) {
            int p = pid[sub][zz];
            if (p >= 0) {
                float2 f = *(const float2*)(feats + (size_t)p*CC + 2*c2);
                v = __floats2half2_rn(f.x, f.y);
            }
        }
        SHIFT1(w, v);
        g_h1[(base + z)*128 + c2] = max7h(w);
    }
}

// y-pass: dense fp16, 2 half2 streams/thread, 4 cols/block.
__global__ __launch_bounds__(256) void k_pool_y() {
    int sub  = threadIdx.x >> 6;             // 0..3
    int lane = threadIdx.x & 63;
    int col  = blockIdx.x * 4 + sub;         // x*64 + z
    int x = col >> 6, z = col & 63;
    int c2 = lane * 2;
    size_t base = (size_t)x * 4096 + z;      // lin(y) = base + y*64

    const __half2 NEG2 = __float2half2_rn(NEGINF);
    __half2 wa[7], wb[7];
    #pragma unroll
    for (int i = 0; i < 7; i++) { wa[i] = NEG2; wb[i] = NEG2; }

    #pragma unroll
    for (int yy = 0; yy < 3; yy++) {
        uint2 r = *(const uint2*)&g_h1[(base + (size_t)yy*64)*128 + c2];
        SHIFT1(wa, *(__half2*)&r.x);
        SHIFT1(wb, *(__half2*)&r.y);
    }
    #pragma unroll 4
    for (int y = 0; y < DD; y++) {
        int yy = y + 3;
        __half2 va = NEG2, vb = NEG2;
        if (yy < DD) {
            uint2 r = *(const uint2*)&g_h1[(base + (size_t)yy*64)*128 + c2];
            va = *(__half2*)&r.x; vb = *(__half2*)&r.y;
        }
        SHIFT1(wa, va); SHIFT1(wb, vb);
        __half2 o0 = max7h(wa), o1 = max7h(wb);
        uint2 out; out.x = *(unsigned*)&o0; out.y = *(unsigned*)&o1;
        *(uint2*)&g_h2[(base + (size_t)y*64)*128 + c2] = out;
    }
}

// x-pass fused with gather: dense read, emit only occupied rows to g_y.
__global__ __launch_bounds__(256) void k_pool_x_gather() {
    int sub  = threadIdx.x >> 6;             // 0..3
    int lane = threadIdx.x & 63;
    int colbase = blockIdx.x * 4;            // y*64 + z
    int col = colbase + sub;
    int c2 = lane * 2;

    __shared__ int pid[4][DD];
    {   int s = threadIdx.x >> 6, xi = threadIdx.x & 63;
        pid[s][xi] = g_idx[(size_t)xi*4096 + colbase + s]; }
    __syncthreads();

    const __half2 NEG2 = __float2half2_rn(NEGINF);
    __half2 wa[7], wb[7];
    #pragma unroll
    for (int i = 0; i < 7; i++) { wa[i] = NEG2; wb[i] = NEG2; }

    size_t base = (size_t)col;               // lin(x) = base + x*4096
    #pragma unroll
    for (int xx = 0; xx < 3; xx++) {
        uint2 r = *(const uint2*)&g_h2[(base + (size_t)xx*4096)*128 + c2];
        SHIFT1(wa, *(__half2*)&r.x);
        SHIFT1(wb, *(__half2*)&r.y);
    }
    #pragma unroll 4
    for (int x = 0; x < DD; x++) {
        int xx = x + 3;
        __half2 va = NEG2, vb = NEG2;
        if (xx < DD) {
            uint2 r = *(const uint2*)&g_h2[(base + (size_t)xx*4096)*128 + c2];
            va = *(__half2*)&r.x; vb = *(__half2*)&r.y;
        }
        SHIFT1(wa, va); SHIFT1(wb, vb);
        int p = pid[sub][x];
        if (p >= 0) {
            __half2 o0 = max7h(wa), o1 = max7h(wb);
            uint2 out; out.x = *(unsigned*)&o0; out.y = *(unsigned*)&o1;
            *(uint2*)&g_y[(size_t)p*128 + c2] = out;
        }
    }
}

// ---------------- fused MLP: out = feats * sigmoid(relu(y@W1)@W2) ----------
// tf32 mma.sync m16n8k8; 512 threads = 16 warps (8 M x 2 N); 256 rows/CTA.

__device__ __forceinline__ unsigned f2tf(float f) {
    unsigned u; asm("cvt.rna.tf32.f32 %0, %1;" : "=r"(u) : "f"(f)); return u;
}
__device__ __forceinline__ void mma8(float* d, const unsigned* a, const unsigned* b,
                                     const float* c) {
    asm volatile("mma.sync.aligned.m16n8k8.row.col.f32.tf32.tf32.f32 "
        "{%0,%1,%2,%3}, {%4,%5,%6,%7}, {%8,%9}, {%10,%11,%12,%13};"
        : "=f"(d[0]),"=f"(d[1]),"=f"(d[2]),"=f"(d[3])
        : "r"(a[0]),"r"(a[1]),"r"(a[2]),"r"(a[3]),
          "r"(b[0]),"r"(b[1]),
          "f"(c[0]),"f"(c[1]),"f"(c[2]),"f"(c[3]));
}

#define SW1S 260                   // sW1T [128 n][260] u32
#define SW2S 132                   // sW2T [256 n][132] u32
#define SHS_H 136                  // sH   [256 m][136] half
#define REGION0_WORDS 33792        // max(128*260, 256*132)
#define MLP_SMEM_BYTES ((REGION0_WORDS*4) + 256*SHS_H*2)   // 135168 + 69632 = 204800

__global__ __launch_bounds__(512, 1) void k_mlp(
    const float* __restrict__ feats, const float* __restrict__ W1,
    const float* __restrict__ W2, float* __restrict__ out) {
    extern __shared__ unsigned sm[];
    unsigned* sW1T = sm;                     // phase A
    unsigned* sW2T = sm;                     // phase B
    __half*   sH   = (__half*)(sm + REGION0_WORDS);

    int tid = threadIdx.x;
    int lane = tid & 31, wid = tid >> 5;
    int group = lane >> 2, tg = lane & 3;
    int warpM = wid & 7, warpN = wid >> 3;   // 8 x 2
    int m0 = blockIdx.x * 256;
    const __half* Yh = (const __half*)g_y;

    // load W1 transposed (tf32 bits)
    for (int idx = tid; idx < CC*RR; idx += 512) {
        int k = idx >> 7, n = idx & 127;
        sW1T[n*SW1S + k] = f2tf(W1[idx]);
    }
    __syncthreads();

    // ---- GEMM1: H[256][128] = Y @ W1, A from global fp16, B from smem ----
    int rowbase = warpM * 32;
    int colbase = warpN * 64;
    {
        float acc[2][8][4];
        #pragma unroll
        for (int mt = 0; mt < 2; mt++)
            #pragma unroll
            for (int nt = 0; nt < 8; nt++)
                #pragma unroll
                for (int q = 0; q < 4; q++) acc[mt][nt][q] = 0.f;

        for (int k0 = 0; k0 < CC; k0 += 8) {
            unsigned a[2][4];
            #pragma unroll
            for (int mt = 0; mt < 2; mt++) {
                int r0i = m0 + rowbase + mt*16 + group;
                int r1i = r0i + 8;
                if (r0i >= NPTS) r0i = NPTS - 1;
                if (r1i >= NPTS) r1i = NPTS - 1;
                size_t r  = (size_t)r0i * CC;
                size_t r8 = (size_t)r1i * CC;
                a[mt][0] = f2tf(__half2float(Yh[r  + k0 + tg]));
                a[mt][1] = f2tf(__half2float(Yh[r8 + k0 + tg]));
                a[mt][2] = f2tf(__half2float(Yh[r  + k0 + tg + 4]));
                a[mt][3] = f2tf(__half2float(Yh[r8 + k0 + tg + 4]));
            }
            unsigned b[8][2];
            #pragma unroll
            for (int nt = 0; nt < 8; nt++) {
                int n = colbase + nt*8 + group;
                b[nt][0] = sW1T[n*SW1S + k0 + tg];
                b[nt][1] = sW1T[n*SW1S + k0 + tg + 4];
            }
            #pragma unroll
            for (int mt = 0; mt < 2; mt++)
                #pragma unroll
                for (int nt = 0; nt < 8; nt++)
                    mma8(acc[mt][nt], a[mt], b[nt], acc[mt][nt]);
        }

        // relu -> sH as fp16 (same mantissa as tf32; no extra error class)
        #pragma unroll
        for (int mt = 0; mt < 2; mt++)
            #pragma unroll
            for (int nt = 0; nt < 8; nt++) {
                int rl = rowbase + mt*16 + group;
                int cl = colbase + nt*8 + 2*tg;
                __half2 h0 = __floats2half2_rn(fmaxf(acc[mt][nt][0],0.f),
                                               fmaxf(acc[mt][nt][1],0.f));
                __half2 h1 = __floats2half2_rn(fmaxf(acc[mt][nt][2],0.f),
                                               fmaxf(acc[mt][nt][3],0.f));
                *(__half2*)&sH[rl*SHS_H + cl]       = h0;
                *(__half2*)&sH[(rl+8)*SHS_H + cl]   = h1;
            }
    }
    __syncthreads();

    // load W2 transposed (overwrites W1T region)
    for (int idx = tid; idx < RR*CC; idx += 512) {
        int k = idx >> 8, n = idx & 255;
        sW2T[n*SW2S + k] = f2tf(W2[idx]);
    }
    __syncthreads();

    // ---- GEMM2: Z = relu(H) @ W2, two 64-col passes per warp ----
    for (int p = 0; p < 2; p++) {
        int cb = warpN*128 + p*64;
        float acc2[2][8][4];
        #pragma unroll
        for (int mt = 0; mt < 2; mt++)
            #pragma unroll
            for (int nt = 0; nt < 8; nt++)
                #pragma unroll
                for (int q = 0; q < 4; q++) acc2[mt][nt][q] = 0.f;

        for (int k0 = 0; k0 < RR; k0 += 8) {
            unsigned a[2][4];
            #pragma unroll
            for (int mt = 0; mt < 2; mt++) {
                int rl = rowbase + mt*16 + group;
                a[mt][0] = f2tf(__half2float(sH[rl*SHS_H + k0 + tg]));
                a[mt][1] = f2tf(__half2float(sH[(rl+8)*SHS_H + k0 + tg]));
                a[mt][2] = f2tf(__half2float(sH[rl*SHS_H + k0 + tg + 4]));
                a[mt][3] = f2tf(__half2float(sH[(rl+8)*SHS_H + k0 + tg + 4]));
            }
            unsigned b[8][2];
            #pragma unroll
            for (int nt = 0; nt < 8; nt++) {
                int n = cb + nt*8 + group;
                b[nt][0] = sW2T[n*SW2S + k0 + tg];
                b[nt][1] = sW2T[n*SW2S + k0 + tg + 4];
            }
            #pragma unroll
            for (int mt = 0; mt < 2; mt++)
                #pragma unroll
                for (int nt = 0; nt < 8; nt++)
                    mma8(acc2[mt][nt], a[mt], b[nt], acc2[mt][nt]);
        }

        // epilogue: sigmoid, multiply feats, store
        #pragma unroll
        for (int mt = 0; mt < 2; mt++)
            #pragma unroll
            for (int nt = 0; nt < 8; nt++) {
                int rl = rowbase + mt*16 + group;
                int cl = cb + nt*8 + 2*tg;
                int gi0 = m0 + rl, gi1 = gi0 + 8;
                if (gi0 < NPTS) {
                    float2 f = *(const float2*)(feats + (size_t)gi0*CC + cl);
                    float s0 = 1.f/(1.f + __expf(-acc2[mt][nt][0]));
                    float s1 = 1.f/(1.f + __expf(-acc2[mt][nt][1]));
                    float2 o; o.x = f.x*s0; o.y = f.y*s1;
                    *(float2*)(out + (size_t)gi0*CC + cl) = o;
                }
                if (gi1 < NPTS) {
                    float2 f = *(const float2*)(feats + (size_t)gi1*CC + cl);
                    float s2 = 1.f/(1.f + __expf(-acc2[mt][nt][2]));
                    float s3 = 1.f/(1.f + __expf(-acc2[mt][nt][3]));
                    float2 o; o.x = f.x*s2; o.y = f.y*s3;
                    *(float2*)(out + (size_t)gi1*CC + cl) = o;
                }
            }
    }
}

// ---------------- launch ----------------------------------------------------
extern "C" void kernel_launch(void* const* d_in, const int* in_sizes, int n_in,
                              void* d_out, int out_size) {
    const float* feats  = (const float*)d_in[0];
    const int*   coords = (const int*)d_in[1];
    const float* W1     = (const float*)d_in[2];
    const float* W2     = (const float*)d_in[3];
    float*       out    = (float*)d_out;

    k_init_idx<<<(VV + 255)/256, 256>>>();
    k_scatter<<<(NPTS + 255)/256, 256>>>(coords);
    k_pool_z<<<DD*DD/2, 256>>>(feats);
    k_pool_y<<<DD*DD/4, 256>>>();
    k_pool_x_gather<<<DD*DD/4, 256>>>();

    cudaFuncSetAttribute(k_mlp, cudaFuncAttributeMaxDynamicSharedMemorySize,
                         MLP_SMEM_BYTES);
    int nblk = (NPTS + 255) / 256;   // 391
    k_mlp<<<nblk, 512, MLP_SMEM_BYTES>>>(feats, W1, W2, out);
}

// round 3
// speedup vs baseline: 2.0983x; 1.1145x over previous
#include <cuda_runtime.h>
#include <cuda_fp16.h>
#include <math.h>
#include <stdint.h>

#define DD 64
#define CC 256
#define RR 128
#define NPTS 100000
#define VV (DD*DD*DD)

// ---------------- scratch (static device globals; no allocations) ----------
__device__ int     g_idx  [VV];               // [x][y][z] -> point or -1
__device__ int     g_idx_t[VV];               // [z][x*64+y] -> point or -1
// z-passed grid, layout [z][cs][xy][8 half2]  (cs = channel slice of 16 ch)
__device__ __half2 g_h1[(size_t)VV * 128];
__device__ __half2 g_y [(size_t)NPTS * 128];  // gathered pooled features (row-major, 256 half)

#define NEGINF (-INFINITY)

// ---------------- index grids ----------------------------------------------
__global__ void k_init_idx() {
    int i = blockIdx.x * blockDim.x + threadIdx.x;
    if (i < VV) { g_idx[i] = -1; g_idx_t[i] = -1; }
}

__global__ void k_scatter(const int* __restrict__ coords) {
    int i = blockIdx.x * blockDim.x + threadIdx.x;
    if (i < NPTS) {
        int ix = coords[3*i], iy = coords[3*i+1], iz = coords[3*i+2];
        g_idx  [(ix*DD + iy)*DD + iz]   = i;
        g_idx_t[iz*4096 + ix*DD + iy]   = i;
    }
}

// ---------------- helpers ---------------------------------------------------
#define SHIFT1(w, v) do { w[6]=w[5]; w[5]=w[4]; w[4]=w[3]; w[3]=w[2]; w[2]=w[1]; w[1]=w[0]; w[0]=(v); } while(0)
__device__ __forceinline__ __half2 max7h(const __half2* w) {
    return __hmax2(__hmax2(__hmax2(w[0],w[1]),__hmax2(w[2],w[3])),
                   __hmax2(__hmax2(w[4],w[5]),w[6]));
}

// ---------------- z-pass: gather feats, slide along z, write [z][cs][xy][c] -
// grid: 128 column-blocks (32 (x,y) cols each) x 16 channel slices = 2048 CTAs
__global__ __launch_bounds__(256) void k_pool_z(const float* __restrict__ feats) {
    int cb = blockIdx.x >> 4;          // column block: columns cb*32 .. +31
    int cs = blockIdx.x & 15;          // channel slice (16 ch = 8 half2)
    int cl = threadIdx.x >> 3;         // 0..31 column within block
    int c  = threadIdx.x & 7;          // half2 within slice

    __shared__ int pid[32*DD];
    #pragma unroll
    for (int k = 0; k < 8; k++)
        pid[threadIdx.x + 256*k] = g_idx[cb*2048 + threadIdx.x + 256*k];
    __syncthreads();

    const __half2 NEG2 = __float2half2_rn(NEGINF);
    __half2 w[7];
    #pragma unroll
    for (int i = 0; i < 7; i++) w[i] = NEG2;

    const int xy = cb*32 + cl;
    const float* fbase = feats + cs*16 + c*2;

    #pragma unroll
    for (int zz = 0; zz < 3; zz++) {
        int p = pid[cl*DD + zz];
        __half2 v = NEG2;
        if (p >= 0) {
            float2 f = *(const float2*)(fbase + (size_t)p*CC);
            v = __floats2half2_rn(f.x, f.y);
        }
        SHIFT1(w, v);
    }
    #pragma unroll 4
    for (int z = 0; z < DD; z++) {
        int zz = z + 3;
        __half2 v = NEG2;
        if (zz < DD) {
            int p = pid[cl*DD + zz];
            if (p >= 0) {
                float2 f = *(const float2*)(fbase + (size_t)p*CC);
                v = __floats2half2_rn(f.x, f.y);
            }
        }
        SHIFT1(w, v);
        g_h1[((size_t)(z*16 + cs)*4096 + xy)*8 + c] = max7h(w);
    }
}

// ---------------- fused y-pass + x-pass + gather ----------------------------
// grid: 64 z-slices x 16 channel slices = 1024 CTAs, 256 threads.
// smem tile: [x][y][8 half2] with padded x-stride of 520 words.
#define TXS 520                                    // words per x row
#define YX_SMEM_BYTES ((64*TXS + 4096) * 4)        // 133120 + 16384 = 149504

__global__ __launch_bounds__(256) void k_pool_yx() {
    extern __shared__ unsigned smw[];
    unsigned* sT  = smw;                 // tile, word = half2
    int*      spid = (int*)(smw + 64*TXS);

    int z  = blockIdx.x >> 4;
    int cs = blockIdx.x & 15;
    int tid = threadIdx.x;

    // load slab (contiguous 131072 B) into padded tile
    const uint4* src = (const uint4*)(g_h1 + (size_t)(z*16 + cs)*32768);
    #pragma unroll
    for (int k = 0; k < 32; k++) {
        int q = tid + 256*k;             // uint4 chunk index
        uint4 v = src[q];
        int w0 = q*4;
        int xy = w0 >> 3, c0 = w0 & 7;
        *(uint4*)&sT[(xy>>6)*TXS + (xy&63)*8 + c0] = v;
    }
    // load transposed idx for this z-slice
    {
        const uint4* isrc = (const uint4*)(g_idx_t + z*4096);
        #pragma unroll
        for (int k = 0; k < 4; k++)
            *(uint4*)&spid[(tid + 256*k)*4] = isrc[tid + 256*k];
    }
    __syncthreads();

    const __half2 NEG2 = __float2half2_rn(NEGINF);

    // ---- y-pass, in-place in smem. column = (x, c), 512 cols / 256 thr ----
    #pragma unroll
    for (int rep = 0; rep < 2; rep++) {
        int q = tid + 256*rep;
        int x = q >> 3, c = q & 7;
        unsigned* col = sT + x*TXS + c;
        __half2 w[7];
        #pragma unroll
        for (int i = 0; i < 7; i++) w[i] = NEG2;
        #pragma unroll
        for (int yy = 0; yy < 3; yy++) { unsigned r = col[yy*8]; SHIFT1(w, *(__half2*)&r); }
        #pragma unroll 4
        for (int y = 0; y < DD; y++) {
            int yy = y + 3;
            __half2 v = NEG2;
            if (yy < DD) { unsigned r = col[yy*8]; v = *(__half2*)&r; }
            SHIFT1(w, v);
            __half2 o = max7h(w);
            col[y*8] = *(unsigned*)&o;
        }
    }
    __syncthreads();

    // ---- x-pass + sparse gather. column = (y, c) ----
    #pragma unroll
    for (int rep = 0; rep < 2; rep++) {
        int q = tid + 256*rep;
        int y = q >> 3, c = q & 7;
        unsigned* col = sT + y*8 + c;
        __half2 w[7];
        #pragma unroll
        for (int i = 0; i < 7; i++) w[i] = NEG2;
        #pragma unroll
        for (int xx = 0; xx < 3; xx++) { unsigned r = col[xx*TXS]; SHIFT1(w, *(__half2*)&r); }
        #pragma unroll 4
        for (int x = 0; x < DD; x++) {
            int xx = x + 3;
            __half2 v = NEG2;
            if (xx < DD) { unsigned r = col[xx*TXS]; v = *(__half2*)&r; }
            SHIFT1(w, v);
            int p = spid[x*64 + y];
            if (p >= 0) g_y[(size_t)p*128 + cs*8 + c] = max7h(w);
        }
    }
}

// ---------------- fused MLP: out = feats * sigmoid(relu(y@W1)@W2) ----------
// fp16 mma m16n8k16; 512 threads = 16 warps (8 M x 2 N); 256 rows/CTA.

__device__ __forceinline__ uint32_t s2u(const void* p) {
    return (uint32_t)__cvta_generic_to_shared(p);
}
__device__ __forceinline__ void ldmA(uint32_t* a, const void* p) {
    asm volatile("ldmatrix.sync.aligned.m8n8.x4.shared.b16 {%0,%1,%2,%3}, [%4];"
        : "=r"(a[0]),"=r"(a[1]),"=r"(a[2]),"=r"(a[3]) : "r"(s2u(p)));
}
__device__ __forceinline__ void mma16(float* d, const uint32_t* a, const uint32_t* b,
                                      const float* c) {
    asm volatile("mma.sync.aligned.m16n8k16.row.col.f32.f16.f16.f32 "
        "{%0,%1,%2,%3}, {%4,%5,%6,%7}, {%8,%9}, {%10,%11,%12,%13};"
        : "=f"(d[0]),"=f"(d[1]),"=f"(d[2]),"=f"(d[3])
        : "r"(a[0]),"r"(a[1]),"r"(a[2]),"r"(a[3]),
          "r"(b[0]),"r"(b[1]),
          "f"(c[0]),"f"(c[1]),"f"(c[2]),"f"(c[3]));
}

#define SAS 264                     // sA [256 m][264] half (also sH region)
#define SWS 264                     // sW1T [128 n][264] half
#define SW2S_H 136                  // sW2T [256 n][136] half
#define SHS_H 136                   // sH [256 m][136] half (inside sA region)
#define AW_HALFS (256*SAS)          // 67584 halfs = 135168 B
#define MLP_SMEM_BYTES (AW_HALFS*2 + 256*SW2S_H*2)   // 135168 + 69632 = 204800

__global__ __launch_bounds__(512, 1) void k_mlp(
    const float* __restrict__ feats, const float* __restrict__ W1,
    const float* __restrict__ W2, float* __restrict__ out) {
    extern __shared__ __half smh[];
    __half* sA  = smh;                       // phase A: A tile; phase B: sH
    __half* sW  = smh + AW_HALFS;            // phase A: W1T; phase B: W2T
    __half* sH  = smh;

    int tid = threadIdx.x;
    int lane = tid & 31, wid = tid >> 5;
    int group = lane >> 2, tg = lane & 3;
    int warpM = wid & 7, warpN = wid >> 3;   // 8 x 2
    int rowbase = warpM * 32;
    int colbase = warpN * 64;
    int m0 = blockIdx.x * 256;

    // stage A tile (256 rows x 256 halfs) from g_y with uint4 loads
    {
        const __half* Yh = (const __half*)g_y;
        #pragma unroll
        for (int k = 0; k < 16; k++) {
            int u = tid + 512*k;             // uint4 index, 8192 total
            int row = u >> 5, cw = (u & 31)*8;
            int gr = m0 + row; if (gr >= NPTS) gr = NPTS - 1;
            uint4 v = *(const uint4*)(Yh + (size_t)gr*CC + cw);
            *(uint4*)&sA[row*SAS + cw] = v;
        }
    }
    // stage W1 transposed as fp16
    for (int idx = tid; idx < CC*RR; idx += 512) {
        int k = idx >> 7, n = idx & 127;
        sW[n*SWS + k] = __float2half(W1[idx]);
    }
    __syncthreads();

    // ---- GEMM1: H[256][128] = A @ W1 ----
    int lrow = lane & 15;
    int lk   = (lane >> 4) * 8;
    {
        float acc[2][8][4];
        #pragma unroll
        for (int mt = 0; mt < 2; mt++)
            #pragma unroll
            for (int nt = 0; nt < 8; nt++)
                #pragma unroll
                for (int q = 0; q < 4; q++) acc[mt][nt][q] = 0.f;

        for (int k0 = 0; k0 < CC; k0 += 16) {
            uint32_t a[2][4];
            #pragma unroll
            for (int mt = 0; mt < 2; mt++)
                ldmA(a[mt], &sA[(rowbase + mt*16 + lrow)*SAS + k0 + lk]);
            uint32_t b[8][2];
            #pragma unroll
            for (int nt = 0; nt < 8; nt++) {
                int n = colbase + nt*8 + group;
                b[nt][0] = *(const uint32_t*)&sW[n*SWS + k0 + 2*tg];
                b[nt][1] = *(const uint32_t*)&sW[n*SWS + k0 + 2*tg + 8];
            }
            #pragma unroll
            for (int mt = 0; mt < 2; mt++)
                #pragma unroll
                for (int nt = 0; nt < 8; nt++)
                    mma16(acc[mt][nt], a[mt], b[nt], acc[mt][nt]);
        }
        __syncthreads();   // everyone done reading sA / sW

        // relu -> sH (fp16, reuses sA region); stage W2 (reuses sW region)
        #pragma unroll
        for (int mt = 0; mt < 2; mt++)
            #pragma unroll
            for (int nt = 0; nt < 8; nt++) {
                int rl = rowbase + mt*16 + group;
                int cl = colbase + nt*8 + 2*tg;
                __half2 h0 = __floats2half2_rn(fmaxf(acc[mt][nt][0],0.f),
                                               fmaxf(acc[mt][nt][1],0.f));
                __half2 h1 = __floats2half2_rn(fmaxf(acc[mt][nt][2],0.f),
                                               fmaxf(acc[mt][nt][3],0.f));
                *(__half2*)&sH[rl*SHS_H + cl]     = h0;
                *(__half2*)&sH[(rl+8)*SHS_H + cl] = h1;
            }
    }
    for (int idx = tid; idx < RR*CC; idx += 512) {
        int k = idx >> 8, n = idx & 255;
        sW[n*SW2S_H + k] = __float2half(W2[idx]);
    }
    __syncthreads();

    // ---- GEMM2: Z = H @ W2, two 64-col passes per warp ----
    for (int p = 0; p < 2; p++) {
        int cb = warpN*128 + p*64;
        float acc2[2][8][4];
        #pragma unroll
        for (int mt = 0; mt < 2; mt++)
            #pragma unroll
            for (int nt = 0; nt < 8; nt++)
                #pragma unroll
                for (int q = 0; q < 4; q++) acc2[mt][nt][q] = 0.f;

        for (int k0 = 0; k0 < RR; k0 += 16) {
            uint32_t a[2][4];
            #pragma unroll
            for (int mt = 0; mt < 2; mt++)
                ldmA(a[mt], &sH[(rowbase + mt*16 + lrow)*SHS_H + k0 + lk]);
            uint32_t b[8][2];
            #pragma unroll
            for (int nt = 0; nt < 8; nt++) {
                int n = cb + nt*8 + group;
                b[nt][0] = *(const uint32_t*)&sW[n*SW2S_H + k0 + 2*tg];
                b[nt][1] = *(const uint32_t*)&sW[n*SW2S_H + k0 + 2*tg + 8];
            }
            #pragma unroll
            for (int mt = 0; mt < 2; mt++)
                #pragma unroll
                for (int nt = 0; nt < 8; nt++)
                    mma16(acc2[mt][nt], a[mt], b[nt], acc2[mt][nt]);
        }

        // epilogue: sigmoid, multiply feats, store
        #pragma unroll
        for (int mt = 0; mt < 2; mt++)
            #pragma unroll
            for (int nt = 0; nt < 8; nt++) {
                int rl = rowbase + mt*16 + group;
                int cl = cb + nt*8 + 2*tg;
                int gi0 = m0 + rl, gi1 = gi0 + 8;
                if (gi0 < NPTS) {
                    float2 f = *(const float2*)(feats + (size_t)gi0*CC + cl);
                    float s0 = 1.f/(1.f + __expf(-acc2[mt][nt][0]));
                    float s1 = 1.f/(1.f + __expf(-acc2[mt][nt][1]));
                    float2 o; o.x = f.x*s0; o.y = f.y*s1;
                    *(float2*)(out + (size_t)gi0*CC + cl) = o;
                }
                if (gi1 < NPTS) {
                    float2 f = *(const float2*)(feats + (size_t)gi1*CC + cl);
                    float s2 = 1.f/(1.f + __expf(-acc2[mt][nt][2]));
                    float s3 = 1.f/(1.f + __expf(-acc2[mt][nt][3]));
                    float2 o; o.x = f.x*s2; o.y = f.y*s3;
                    *(float2*)(out + (size_t)gi1*CC + cl) = o;
                }
            }
    }
}

// ---------------- launch ----------------------------------------------------
extern "C" void kernel_launch(void* const* d_in, const int* in_sizes, int n_in,
                              void* d_out, int out_size) {
    const float* feats  = (const float*)d_in[0];
    const int*   coords = (const int*)d_in[1];
    const float* W1     = (const float*)d_in[2];
    const float* W2     = (const float*)d_in[3];
    float*       out    = (float*)d_out;

    k_init_idx<<<(VV + 255)/256, 256>>>();
    k_scatter<<<(NPTS + 255)/256, 256>>>(coords);
    k_pool_z<<<2048, 256>>>(feats);

    cudaFuncSetAttribute(k_pool_yx, cudaFuncAttributeMaxDynamicSharedMemorySize,
                         YX_SMEM_BYTES);
    k_pool_yx<<<1024, 256, YX_SMEM_BYTES>>>();

    cudaFuncSetAttribute(k_mlp, cudaFuncAttributeMaxDynamicSharedMemorySize,
                         MLP_SMEM_BYTES);
    int nblk = (NPTS + 255) / 256;   // 391
    k_mlp<<<nblk, 512, MLP_SMEM_BYTES>>>(feats, W1, W2, out);
}

// round 5
// speedup vs baseline: 2.5863x; 1.2326x over previous
#include <cuda_runtime.h>
#include <cuda_fp16.h>
#include <math.h>
#include <stdint.h>

#define DD 64
#define CC 256
#define RR 128
#define NPTS 100000
#define VV (DD*DD*DD)

// ---------------- scratch (static device globals; no allocations) ----------
__device__ int     g_idx  [VV];               // [x][y][z] -> point or -1
__device__ int     g_idx_t[VV];               // [z][x*64+y] -> point or -1
// z-passed grid, layout [z][cs][xy][8 half2]  (cs = channel slice of 16 ch)
__device__ __half2 g_h1[(size_t)VV * 128];
__device__ __half2 g_y [(size_t)NPTS * 128];  // gathered pooled features

#define SWS    264                 // sW1T [128 n][264] half
#define SW2S_H 136                 // sW2T [256 n][136] half
__device__ __align__(16) __half g_w1p[RR*SWS];     // prepacked W1^T, padded
__device__ __align__(16) __half g_w2p[CC*SW2S_H];  // prepacked W2^T, padded

#define NEGINF (-INFINITY)

// ---------------- index grids + weight prepack ------------------------------
__global__ void k_init_idx() {
    int i = blockIdx.x * blockDim.x + threadIdx.x;
    if (i < VV) { g_idx[i] = -1; g_idx_t[i] = -1; }
}

__global__ void k_scatter(const int* __restrict__ coords) {
    int i = blockIdx.x * blockDim.x + threadIdx.x;
    if (i < NPTS) {
        int ix = coords[3*i], iy = coords[3*i+1], iz = coords[3*i+2];
        g_idx  [(ix*DD + iy)*DD + iz] = i;
        g_idx_t[iz*4096 + ix*DD + iy] = i;
    }
}

__global__ void k_prepack(const float* __restrict__ W1, const float* __restrict__ W2) {
    int i = blockIdx.x * blockDim.x + threadIdx.x;   // 0..32767
    { int k = i >> 7, n = i & 127; g_w1p[n*SWS    + k] = __float2half(W1[i]); }
    { int k = i >> 8, n = i & 255; g_w2p[n*SW2S_H + k] = __float2half(W2[i]); }
}

// ---------------- helpers ---------------------------------------------------
#define SHIFT1(w, v) do { w[6]=w[5]; w[5]=w[4]; w[4]=w[3]; w[3]=w[2]; w[2]=w[1]; w[1]=w[0]; w[0]=(v); } while(0)
__device__ __forceinline__ __half2 max7h(const __half2* w) {
    return __hmax2(__hmax2(__hmax2(w[0],w[1]),__hmax2(w[2],w[3])),
                   __hmax2(__hmax2(w[4],w[5]),w[6]));
}

// ---------------- z-pass: gather feats, slide along z, write [z][cs][xy][c] -
__global__ __launch_bounds__(256) void k_pool_z(const float* __restrict__ feats) {
    int cb = blockIdx.x >> 4;          // column block: columns cb*32 .. +31
    int cs = blockIdx.x & 15;          // channel slice (16 ch = 8 half2)
    int cl = threadIdx.x >> 3;         // 0..31 column within block
    int c  = threadIdx.x & 7;          // half2 within slice

    __shared__ int pid[32*DD];
    #pragma unroll
    for (int k = 0; k < 8; k++)
        pid[threadIdx.x + 256*k] = g_idx[cb*2048 + threadIdx.x + 256*k];
    __syncthreads();

    const __half2 NEG2 = __float2half2_rn(NEGINF);
    __half2 w[7];
    #pragma unroll
    for (int i = 0; i < 7; i++) w[i] = NEG2;

    const int xy = cb*32 + cl;
    const float* fbase = feats + cs*16 + c*2;

    #pragma unroll
    for (int zz = 0; zz < 3; zz++) {
        int p = pid[cl*DD + zz];
        __half2 v = NEG2;
        if (p >= 0) {
            float2 f = *(const float2*)(fbase + (size_t)p*CC);
            v = __floats2half2_rn(f.x, f.y);
        }
        SHIFT1(w, v);
    }
    #pragma unroll 4
    for (int z = 0; z < DD; z++) {
        int zz = z + 3;
        __half2 v = NEG2;
        if (zz < DD) {
            int p = pid[cl*DD + zz];
            if (p >= 0) {
                float2 f = *(const float2*)(fbase + (size_t)p*CC);
                v = __floats2half2_rn(f.x, f.y);
            }
        }
        SHIFT1(w, v);
        g_h1[((size_t)(z*16 + cs)*4096 + xy)*8 + c] = max7h(w);
    }
}

// ---------------- fused y-pass + x-pass + gather (512 threads) --------------
// grid: 64 z-slices x 16 channel slices = 1024 CTAs.
#define TXS 520                                    // words per x row
#define YX_SMEM_BYTES ((64*TXS + 4096) * 4)        // 149504

__global__ __launch_bounds__(512) void k_pool_yx() {
    extern __shared__ unsigned smw[];
    unsigned* sT  = smw;                 // tile, word = half2
    int*      spid = (int*)(smw + 64*TXS);

    int z  = blockIdx.x >> 4;
    int cs = blockIdx.x & 15;
    int tid = threadIdx.x;

    // load slab (contiguous 131072 B) into padded tile; 16 uint4 per thread
    const uint4* src = (const uint4*)(g_h1 + (size_t)(z*16 + cs)*32768);
    #pragma unroll
    for (int k = 0; k < 16; k++) {
        int q = tid + 512*k;             // uint4 chunk index
        uint4 v = src[q];
        int w0 = q*4;
        int xy = w0 >> 3, c0 = w0 & 7;
        *(uint4*)&sT[(xy>>6)*TXS + (xy&63)*8 + c0] = v;
    }
    // load transposed idx for this z-slice
    {
        const uint4* isrc = (const uint4*)(g_idx_t + z*4096);
        #pragma unroll
        for (int k = 0; k < 2; k++)
            *(uint4*)&spid[(tid + 512*k)*4] = isrc[tid + 512*k];
    }
    __syncthreads();

    const __half2 NEG2 = __float2half2_rn(NEGINF);

    // ---- y-pass, in-place in smem. one column (x, c) per thread ----
    {
        int x = tid >> 3, c = tid & 7;
        unsigned* col = sT + x*TXS + c;
        __half2 w[7];
        #pragma unroll
        for (int i = 0; i < 7; i++) w[i] = NEG2;
        #pragma unroll
        for (int yy = 0; yy < 3; yy++) { unsigned r = col[yy*8]; SHIFT1(w, *(__half2*)&r); }
        #pragma unroll 4
        for (int y = 0; y < DD; y++) {
            int yy = y + 3;
            __half2 v = NEG2;
            if (yy < DD) { unsigned r = col[yy*8]; v = *(__half2*)&r; }
            SHIFT1(w, v);
            __half2 o = max7h(w);
            col[y*8] = *(unsigned*)&o;
        }
    }
    __syncthreads();

    // ---- x-pass + sparse gather. one column (y, c) per thread ----
    {
        int y = tid >> 3, c = tid & 7;
        unsigned* col = sT + y*8 + c;
        __half2 w[7];
        #pragma unroll
        for (int i = 0; i < 7; i++) w[i] = NEG2;
        #pragma unroll
        for (int xx = 0; xx < 3; xx++) { unsigned r = col[xx*TXS]; SHIFT1(w, *(__half2*)&r); }
        #pragma unroll 4
        for (int x = 0; x < DD; x++) {
            int xx = x + 3;
            __half2 v = NEG2;
            if (xx < DD) { unsigned r = col[xx*TXS]; v = *(__half2*)&r; }
            SHIFT1(w, v);
            int p = spid[x*64 + y];
            if (p >= 0) g_y[(size_t)p*128 + cs*8 + c] = max7h(w);
        }
    }
}

// ---------------- fused MLP: out = feats * sigmoid(relu(y@W1)@W2) ----------
// fp16 mma m16n8k16; 512 threads = 16 warps (8 M x 2 N); 256 rows/CTA.

__device__ __forceinline__ uint32_t s2u(const void* p) {
    return (uint32_t)__cvta_generic_to_shared(p);
}
__device__ __forceinline__ void ldmA(uint32_t* a, const void* p) {
    asm volatile("ldmatrix.sync.aligned.m8n8.x4.shared.b16 {%0,%1,%2,%3}, [%4];"
        : "=r"(a[0]),"=r"(a[1]),"=r"(a[2]),"=r"(a[3]) : "r"(s2u(p)));
}
__device__ __forceinline__ void mma16(float* d, const uint32_t* a, const uint32_t* b,
                                      const float* c) {
    asm volatile("mma.sync.aligned.m16n8k16.row.col.f32.f16.f16.f32 "
        "{%0,%1,%2,%3}, {%4,%5,%6,%7}, {%8,%9}, {%10,%11,%12,%13};"
        : "=f"(d[0]),"=f"(d[1]),"=f"(d[2]),"=f"(d[3])
        : "r"(a[0]),"r"(a[1]),"r"(a[2]),"r"(a[3]),
          "r"(b[0]),"r"(b[1]),
          "f"(c[0]),"f"(c[1]),"f"(c[2]),"f"(c[3]));
}

#define SAS 264                     // sA [256 m][264] half (also sH region)
#define SHS_H 136                   // sH [256 m][136] half (inside sA region)
#define AW_HALFS (256*SAS)          // 67584 halfs = 135168 B
#define MLP_SMEM_BYTES (AW_HALFS*2 + 256*SW2S_H*2)   // 204800

__global__ __launch_bounds__(512, 1) void k_mlp(
    const float* __restrict__ feats, float* __restrict__ out) {
    extern __shared__ __half smh[];
    __half* sA  = smh;                       // phase A: A tile; phase B: sH
    __half* sW  = smh + AW_HALFS;            // phase A: W1T; phase B: W2T
    __half* sH  = smh;

    int tid = threadIdx.x;
    int lane = tid & 31, wid = tid >> 5;
    int group = lane >> 2, tg = lane & 3;
    int warpM = wid & 7, warpN = wid >> 3;   // 8 x 2
    int rowbase = warpM * 32;
    int colbase = warpN * 64;
    int m0 = blockIdx.x * 256;

    // stage A tile (256 rows x 256 halfs) from g_y with uint4 loads
    {
        const __half* Yh = (const __half*)g_y;
        #pragma unroll
        for (int k = 0; k < 16; k++) {
            int u = tid + 512*k;             // uint4 index, 8192 total
            int row = u >> 5, cw = (u & 31)*8;
            int gr = m0 + row; if (gr >= NPTS) gr = NPTS - 1;
            uint4 v = *(const uint4*)(Yh + (size_t)gr*CC + cw);
            *(uint4*)&sA[row*SAS + cw] = v;
        }
    }
    // stage prepacked W1T: 128*264/8 = 4224 uint4 -> NINE iterations of 512
    {
        const uint4* wsrc = (const uint4*)g_w1p;
        uint4* wdst = (uint4*)sW;
        #pragma unroll
        for (int k = 0; k < 9; k++) {
            int u = tid + 512*k;
            if (u < (RR*SWS)/8) wdst[u] = wsrc[u];
        }
    }
    __syncthreads();

    // ---- GEMM1: H[256][128] = A @ W1 ----
    int lrow = lane & 15;
    int lk   = (lane >> 4) * 8;
    {
        float acc[2][8][4];
        #pragma unroll
        for (int mt = 0; mt < 2; mt++)
            #pragma unroll
            for (int nt = 0; nt < 8; nt++)
                #pragma unroll
                for (int q = 0; q < 4; q++) acc[mt][nt][q] = 0.f;

        for (int k0 = 0; k0 < CC; k0 += 16) {
            uint32_t a[2][4];
            #pragma unroll
            for (int mt = 0; mt < 2; mt++)
                ldmA(a[mt], &sA[(rowbase + mt*16 + lrow)*SAS + k0 + lk]);
            uint32_t b[8][2];
            #pragma unroll
            for (int nt = 0; nt < 8; nt++) {
                int n = colbase + nt*8 + group;
                b[nt][0] = *(const uint32_t*)&sW[n*SWS + k0 + 2*tg];
                b[nt][1] = *(const uint32_t*)&sW[n*SWS + k0 + 2*tg + 8];
            }
            #pragma unroll
            for (int mt = 0; mt < 2; mt++)
                #pragma unroll
                for (int nt = 0; nt < 8; nt++)
                    mma16(acc[mt][nt], a[mt], b[nt], acc[mt][nt]);
        }
        __syncthreads();   // everyone done reading sA / sW

        // relu -> sH (fp16, reuses sA region)
        #pragma unroll
        for (int mt = 0; mt < 2; mt++)
            #pragma unroll
            for (int nt = 0; nt < 8; nt++) {
                int rl = rowbase + mt*16 + group;
                int cl = colbase + nt*8 + 2*tg;
                __half2 h0 = __floats2half2_rn(fmaxf(acc[mt][nt][0],0.f),
                                               fmaxf(acc[mt][nt][1],0.f));
                __half2 h1 = __floats2half2_rn(fmaxf(acc[mt][nt][2],0.f),
                                               fmaxf(acc[mt][nt][3],0.f));
                *(__half2*)&sH[rl*SHS_H + cl]     = h0;
                *(__half2*)&sH[(rl+8)*SHS_H + cl] = h1;
            }
    }
    // stage prepacked W2T: 256*136/8 = 4352 uint4 -> 9 iterations of 512
    {
        const uint4* wsrc = (const uint4*)g_w2p;
        uint4* wdst = (uint4*)sW;
        #pragma unroll
        for (int k = 0; k < 9; k++) {
            int u = tid + 512*k;
            if (u < (CC*SW2S_H)/8) wdst[u] = wsrc[u];
        }
    }
    __syncthreads();

    // ---- GEMM2: Z = H @ W2, two 64-col passes per warp ----
    for (int p = 0; p < 2; p++) {
        int cb = warpN*128 + p*64;
        float acc2[2][8][4];
        #pragma unroll
        for (int mt = 0; mt < 2; mt++)
            #pragma unroll
            for (int nt = 0; nt < 8; nt++)
                #pragma unroll
                for (int q = 0; q < 4; q++) acc2[mt][nt][q] = 0.f;

        for (int k0 = 0; k0 < RR; k0 += 16) {
            uint32_t a[2][4];
            #pragma unroll
            for (int mt = 0; mt < 2; mt++)
                ldmA(a[mt], &sH[(rowbase + mt*16 + lrow)*SHS_H + k0 + lk]);
            uint32_t b[8][2];
            #pragma unroll
            for (int nt = 0; nt < 8; nt++) {
                int n = cb + nt*8 + group;
                b[nt][0] = *(const uint32_t*)&sW[n*SW2S_H + k0 + 2*tg];
                b[nt][1] = *(const uint32_t*)&sW[n*SW2S_H + k0 + 2*tg + 8];
            }
            #pragma unroll
            for (int mt = 0; mt < 2; mt++)
                #pragma unroll
                for (int nt = 0; nt < 8; nt++)
                    mma16(acc2[mt][nt], a[mt], b[nt], acc2[mt][nt]);
        }

        // epilogue: sigmoid, multiply feats, store
        #pragma unroll
        for (int mt = 0; mt < 2; mt++)
            #pragma unroll
            for (int nt = 0; nt < 8; nt++) {
                int rl = rowbase + mt*16 + group;
                int cl = cb + nt*8 + 2*tg;
                int gi0 = m0 + rl, gi1 = gi0 + 8;
                if (gi0 < NPTS) {
                    float2 f = *(const float2*)(feats + (size_t)gi0*CC + cl);
                    float s0 = 1.f/(1.f + __expf(-acc2[mt][nt][0]));
                    float s1 = 1.f/(1.f + __expf(-acc2[mt][nt][1]));
                    float2 o; o.x = f.x*s0; o.y = f.y*s1;
                    *(float2*)(out + (size_t)gi0*CC + cl) = o;
                }
                if (gi1 < NPTS) {
                    float2 f = *(const float2*)(feats + (size_t)gi1*CC + cl);
                    float s2 = 1.f/(1.f + __expf(-acc2[mt][nt][2]));
                    float s3 = 1.f/(1.f + __expf(-acc2[mt][nt][3]));
                    float2 o; o.x = f.x*s2; o.y = f.y*s3;
                    *(float2*)(out + (size_t)gi1*CC + cl) = o;
                }
            }
    }
}

// ---------------- launch ----------------------------------------------------
extern "C" void kernel_launch(void* const* d_in, const int* in_sizes, int n_in,
                              void* d_out, int out_size) {
    const float* feats  = (const float*)d_in[0];
    const int*   coords = (const int*)d_in[1];
    const float* W1     = (const float*)d_in[2];
    const float* W2     = (const float*)d_in[3];
    float*       out    = (float*)d_out;

    k_prepack<<<128, 256>>>(W1, W2);
    k_init_idx<<<(VV + 255)/256, 256>>>();
    k_scatter<<<(NPTS + 255)/256, 256>>>(coords);
    k_pool_z<<<2048, 256>>>(feats);

    cudaFuncSetAttribute(k_pool_yx, cudaFuncAttributeMaxDynamicSharedMemorySize,
                         YX_SMEM_BYTES);
    k_pool_yx<<<1024, 512, YX_SMEM_BYTES>>>();

    cudaFuncSetAttribute(k_mlp, cudaFuncAttributeMaxDynamicSharedMemorySize,
                         MLP_SMEM_BYTES);
    int nblk = (NPTS + 255) / 256;   // 391
    k_mlp<<<nblk, 512, MLP_SMEM_BYTES>>>(feats, out);
}